// round 16
// baseline (speedup 1.0000x reference)
#include <cuda_runtime.h>
#include <cuda_fp16.h>
#include <cstdint>

#define BATCH 4096
#define WID   1024
#define NMAX  1024

// ---------------- scratch (device globals: allowed) ----------------
__device__ __half  g_Axh[(size_t)BATCH*NMAX];       // x hi (fp16)
__device__ __half  g_Axl[(size_t)BATCH*NMAX];       // x lo (fp16)
__device__ __half  g_Bch[(size_t)BATCH*4*NMAX];     // compressed basis hi (2:4)
__device__ __half  g_Bcl[(size_t)BATCH*4*NMAX];     // compressed basis lo
__device__ uint8_t g_Mb [(size_t)BATCH*NMAX];       // metadata: 1 byte / input
__device__ __half  g_Wxh[(size_t)WID*NMAX];         // base_w hi
__device__ __half  g_Wxl[(size_t)WID*NMAX];         // base_w lo
__device__ __half  g_Ws [(size_t)WID*8*NMAX];       // parity-permuted quantized spline w (exact fp16)
__device__ float   g_X0[(size_t)BATCH*WID];
__device__ float   g_X1[(size_t)BATCH*WID];

// ---------------- helpers ----------------
__device__ __forceinline__ uint32_t smem_u32(const void* p){
    return (uint32_t)__cvta_generic_to_shared(p);
}
__device__ __forceinline__ void cpa16(uint32_t dst, const void* src){
    asm volatile("cp.async.ca.shared.global [%0], [%1], 16;\n" :: "r"(dst), "l"(src));
}
__device__ __forceinline__ void ldsm4(uint32_t* r, uint32_t addr){
    asm volatile("ldmatrix.sync.aligned.m8n8.x4.shared.b16 {%0,%1,%2,%3}, [%4];\n"
        : "=r"(r[0]), "=r"(r[1]), "=r"(r[2]), "=r"(r[3]) : "r"(addr));
}
#define MMA16816(d, a, b0, b1)                                                        \
    asm volatile("mma.sync.aligned.m16n8k16.row.col.f32.f16.f16.f32 "                 \
        "{%0,%1,%2,%3},{%4,%5,%6,%7},{%8,%9},{%0,%1,%2,%3};\n"                        \
        : "+f"((d)[0]), "+f"((d)[1]), "+f"((d)[2]), "+f"((d)[3])                      \
        : "r"((a)[0]), "r"((a)[1]), "r"((a)[2]), "r"((a)[3]), "r"(b0), "r"(b1))
// sparse 2:4 fp16 mma, k32, ordered metadata, selector 0
#define MMASP(d, a, b0, b1, b2, b3, e)                                                \
    asm volatile("mma.sp::ordered_metadata.sync.aligned.m16n8k32.row.col.f32.f16.f16.f32 " \
        "{%0,%1,%2,%3},{%4,%5,%6,%7},{%8,%9,%10,%11},{%0,%1,%2,%3},%12,0x0;\n"        \
        : "+f"((d)[0]), "+f"((d)[1]), "+f"((d)[2]), "+f"((d)[3])                      \
        : "r"((a)[0]), "r"((a)[1]), "r"((a)[2]), "r"((a)[3]),                         \
          "r"(b0), "r"(b1), "r"(b2), "r"(b3), "r"(e))

// swizzled smem address: 128B rows, 16B chunk index XOR (row % 8); k in halves
__device__ __forceinline__ uint32_t swaddr(uint32_t base, int r, int k){
    return base + (r << 7) + ((((k >> 3) ^ r) & 7) << 4) + ((k & 7) << 1);
}

// 256-thread tile loaders
__device__ __forceinline__ void ld256_t256(uint32_t dstBase, const int8_t* g, int strideBytes){
    int t = threadIdx.x;
    #pragma unroll
    for (int i = 0; i < 8; i++){
        int q = t + i*256;
        int r = q >> 3, c = q & 7;
        uint32_t d = dstBase + (r << 7) + (((c ^ r) & 7) << 4);
        cpa16(d, g + (size_t)r * strideBytes + (c << 4));
    }
}
__device__ __forceinline__ void ld128_t256(uint32_t dstBase, const int8_t* g, int strideBytes){
    int t = threadIdx.x;
    #pragma unroll
    for (int i = 0; i < 4; i++){
        int q = t + i*256;
        int r = q >> 3, c = q & 7;
        uint32_t d = dstBase + (r << 7) + (((c ^ r) & 7) << 4);
        cpa16(d, g + (size_t)r * strideBytes + (c << 4));
    }
}

// ============================================================
// sparse spline GEMM (R15 proven-best): C = Bhi@Ws + Blo@Ws
// CTA tile M=256 x N=128, 256 threads (8 warps), warp tile 64x64
// chunk = 16 inputs (true k=128, compressed k=64); 2 stages
// metadata semantics: H4 (diag-verified)
// ============================================================
#define SP_STAGE 102400
#define SP_SMEM  (2*SP_STAGE)

__global__ void __launch_bounds__(256, 1) gemm_sp(
    const __half* __restrict__ Bch, const __half* __restrict__ Bcl,
    const uint8_t* __restrict__ Mb, const __half* __restrict__ Ws,
    float* __restrict__ C, int NIN)
{
    extern __shared__ __align__(128) char smem[];
    uint32_t sb = smem_u32(smem);
    const int tid = threadIdx.x, wid = tid >> 5, lane = tid & 31;
    const int wm = wid & 3, wn = wid >> 2;      // 4x2 warp grid, warp tile 64x64
    const int bm = blockIdx.y * 256, bn = blockIdx.x * 128;
    const int NC = NIN / 16;
    const int msh = (lane & 1) << 4;

    const int8_t*  gH = (const int8_t*)(Bch + (size_t)bm * 4 * NIN);
    const int8_t*  gL = (const int8_t*)(Bcl + (size_t)bm * 4 * NIN);
    const uint8_t* gM = Mb + (size_t)bm * NIN;
    const int8_t*  gW = (const int8_t*)(Ws + (size_t)bn * 8 * NIN);

    auto load_chunk = [&](int c){
        uint32_t base = sb + (c & 1) * SP_STAGE;
        ld256_t256(base,          gH + (size_t)c*128, 8*NIN);
        ld256_t256(base + 32768,  gL + (size_t)c*128, 8*NIN);
        cpa16(base + 65536 + tid*16, gM + (size_t)tid*NIN + c*16);
        ld128_t256(base + 69632,  gW + (size_t)c*256,       16*NIN);
        ld128_t256(base + 86016,  gW + (size_t)c*256 + 128, 16*NIN);
    };

    float acc[4][8][4];
    #pragma unroll
    for (int i=0;i<4;i++)
        #pragma unroll
        for (int j=0;j<8;j++)
            #pragma unroll
            for (int q=0;q<4;q++) acc[i][j][q]=0.0f;

    load_chunk(0); asm volatile("cp.async.commit_group;\n" ::: "memory");
    load_chunk(1); asm volatile("cp.async.commit_group;\n" ::: "memory");

    const int nbase = wn*64 + ((lane >> 4) << 3) + (lane & 7);

    for (int c = 0; c < NC; c++){
        asm volatile("cp.async.wait_group 1;\n" ::: "memory");
        __syncthreads();
        uint32_t base = sb + (c & 1) * SP_STAGE;
        uint32_t sH = base, sL = base + 32768, sM = base + 65536, sW = base + 69632;

        // hoisted metadata: 2x LDS.128 per (i), register extraction, branch-free
        uint32_t meta[4][4];
        #pragma unroll
        for (int i = 0; i < 4; i++){
            int mr = wm*64 + i*16 + (lane >> 2);
            uint32_t a0,a1,a2,a3, c0,c1,c2,c3;
            asm volatile("ld.shared.v4.u32 {%0,%1,%2,%3}, [%4];"
                : "=r"(a0),"=r"(a1),"=r"(a2),"=r"(a3) : "r"(sM + mr*16));
            asm volatile("ld.shared.v4.u32 {%0,%1,%2,%3}, [%4];"
                : "=r"(c0),"=r"(c1),"=r"(c2),"=r"(c3) : "r"(sM + (mr+8)*16));
            meta[i][0] = ((a0>>msh)&0xFFFFu) | (((c0>>msh)&0xFFFFu)<<16);
            meta[i][1] = ((a1>>msh)&0xFFFFu) | (((c1>>msh)&0xFFFFu)<<16);
            meta[i][2] = ((a2>>msh)&0xFFFFu) | (((c2>>msh)&0xFFFFu)<<16);
            meta[i][3] = ((a3>>msh)&0xFFFFu) | (((c3>>msh)&0xFFFFu)<<16);
        }

        #pragma unroll
        for (int s = 0; s < 4; s++){
            int ka = s*16 + ((lane >> 4) << 3);              // compressed col offset
            uint32_t ah[4][4], al[4][4];
            #pragma unroll
            for (int i = 0; i < 4; i++){
                int r = wm*64 + i*16 + (lane & 15);
                ldsm4(ah[i], swaddr(sH, r, ka));
                ldsm4(al[i], swaddr(sL, r, ka));
            }
            int kb = ((s & 1) << 5) + (((lane >> 3) & 1) << 3);
            uint32_t wtb = sW + ((s >> 1) << 14);
            #pragma unroll
            for (int p = 0; p < 4; p++){
                int n = nbase + p*16;
                uint32_t b0[4], b1[4];
                ldsm4(b0, swaddr(wtb, n, kb));
                ldsm4(b1, swaddr(wtb, n, kb + 16));
                // hi pass
                #pragma unroll
                for (int i = 0; i < 4; i++){
                    MMASP(acc[i][2*p+0], ah[i], b0[0], b0[1], b1[0], b1[1], meta[i][s]);
                    MMASP(acc[i][2*p+1], ah[i], b0[2], b0[3], b1[2], b1[3], meta[i][s]);
                }
                // lo pass (same B frags + metadata)
                #pragma unroll
                for (int i = 0; i < 4; i++){
                    MMASP(acc[i][2*p+0], al[i], b0[0], b0[1], b1[0], b1[1], meta[i][s]);
                    MMASP(acc[i][2*p+1], al[i], b0[2], b0[3], b1[2], b1[3], meta[i][s]);
                }
            }
        }
        __syncthreads();
        if (c + 2 < NC) load_chunk(c + 2);
        asm volatile("cp.async.commit_group;\n" ::: "memory");
    }

    // epilogue: write C
    #pragma unroll
    for (int i = 0; i < 4; i++){
        int row = bm + wm*64 + i*16 + (lane >> 2);
        #pragma unroll
        for (int j = 0; j < 8; j++){
            int col = bn + wn*64 + j*8 + ((lane & 3) << 1);
            float* p = C + (size_t)row * WID + col;
            *reinterpret_cast<float2*>(p)         = make_float2(acc[i][j][0], acc[i][j][1]);
            *reinterpret_cast<float2*>(p + 8*WID) = make_float2(acc[i][j][2], acc[i][j][3]);
        }
    }
}

// ============================================================
// fp16 base GEMM: split 3-pass, K = NIN, C +=
// CTA tile M=256 x N=128, 256 threads (8 warps), warp tile 64x64
// ============================================================
#define FB_STAGE 98304
#define FB_SMEM  (2*FB_STAGE)

__global__ void __launch_bounds__(256, 1) gemm_f16base(
    const __half* __restrict__ Axh, const __half* __restrict__ Axl,
    const __half* __restrict__ Wxh, const __half* __restrict__ Wxl,
    float* __restrict__ C, int K)
{
    extern __shared__ __align__(128) char smem[];
    uint32_t sb = smem_u32(smem);
    const int tid = threadIdx.x, wid = tid >> 5, lane = tid & 31;
    const int wm = wid & 3, wn = wid >> 2;      // 4x2 warp grid, warp tile 64x64
    const int bm = blockIdx.y * 256, bn = blockIdx.x * 128;
    const int NC = K / 64;

    const int8_t* gAh = (const int8_t*)(Axh + (size_t)bm * K);
    const int8_t* gAl = (const int8_t*)(Axl + (size_t)bm * K);
    const int8_t* gWh = (const int8_t*)(Wxh + (size_t)bn * K);
    const int8_t* gWl = (const int8_t*)(Wxl + (size_t)bn * K);

    auto load_chunk = [&](int c){
        uint32_t base = sb + (c & 1) * FB_STAGE;
        int kb = c * 128;                      // 64 halves = 128 bytes
        ld256_t256(base,         gAh + kb, 2*K);
        ld256_t256(base + 32768, gAl + kb, 2*K);
        ld128_t256(base + 65536, gWh + kb, 2*K);
        ld128_t256(base + 81920, gWl + kb, 2*K);
    };

    float acc[4][8][4];
    #pragma unroll
    for (int i=0;i<4;i++)
        #pragma unroll
        for (int j=0;j<8;j++)
            #pragma unroll
            for (int q=0;q<4;q++) acc[i][j][q]=0.0f;

    load_chunk(0); asm volatile("cp.async.commit_group;\n" ::: "memory");
    load_chunk(1); asm volatile("cp.async.commit_group;\n" ::: "memory");

    const int nbase = wn*64 + ((lane >> 4) << 3) + (lane & 7);

    for (int c = 0; c < NC; c++){
        asm volatile("cp.async.wait_group 1;\n" ::: "memory");
        __syncthreads();
        uint32_t base = sb + (c & 1) * FB_STAGE;
        uint32_t sAh = base, sAl = base + 32768, sWh = base + 65536, sWl = base + 81920;

        #pragma unroll
        for (int ks = 0; ks < 4; ks++){
            int k0 = ks * 16;
            int ka = k0 + ((lane >> 4) << 3);
            int kb = k0 + (((lane >> 3) & 1) << 3);
            uint32_t ah[4][4], al[4][4];
            #pragma unroll
            for (int i = 0; i < 4; i++){
                int r = wm*64 + i*16 + (lane & 15);
                ldsm4(ah[i], swaddr(sAh, r, ka));
                ldsm4(al[i], swaddr(sAl, r, ka));
            }
            #pragma unroll
            for (int p = 0; p < 4; p++){
                int n = nbase + p*16;
                uint32_t bh[4], bl[4];
                ldsm4(bh, swaddr(sWh, n, kb));
                ldsm4(bl, swaddr(sWl, n, kb));
                // pass 1: Ahi * Whi
                #pragma unroll
                for (int i = 0; i < 4; i++){
                    MMA16816(acc[i][2*p+0], ah[i], bh[0], bh[1]);
                    MMA16816(acc[i][2*p+1], ah[i], bh[2], bh[3]);
                }
                // pass 2: Alo * Whi
                #pragma unroll
                for (int i = 0; i < 4; i++){
                    MMA16816(acc[i][2*p+0], al[i], bh[0], bh[1]);
                    MMA16816(acc[i][2*p+1], al[i], bh[2], bh[3]);
                }
                // pass 3: Ahi * Wlo
                #pragma unroll
                for (int i = 0; i < 4; i++){
                    MMA16816(acc[i][2*p+0], ah[i], bl[0], bl[1]);
                    MMA16816(acc[i][2*p+1], ah[i], bl[2], bl[3]);
                }
            }
        }
        __syncthreads();
        if (c + 2 < NC) load_chunk(c + 2);
        asm volatile("cp.async.commit_group;\n" ::: "memory");
    }

    // epilogue: C +=
    #pragma unroll
    for (int i = 0; i < 4; i++){
        int row = bm + wm*64 + i*16 + (lane >> 2);
        #pragma unroll
        for (int j = 0; j < 8; j++){
            int col = bn + wn*64 + j*8 + ((lane & 3) << 1);
            float* p = C + (size_t)row * WID + col;
            float2 o0 = *reinterpret_cast<float2*>(p);
            float2 o1 = *reinterpret_cast<float2*>(p + 8*WID);
            *reinterpret_cast<float2*>(p)         = make_float2(o0.x + acc[i][j][0], o0.y + acc[i][j][1]);
            *reinterpret_cast<float2*>(p + 8*WID) = make_float2(o1.x + acc[i][j][2], o1.y + acc[i][j][3]);
        }
    }
}

// ---------------- expand A: closed-form cubic B-spline (uniform grid) ----------------
__global__ void expandA_sp(const float* __restrict__ x, int NIN){
    int idx = blockIdx.x*blockDim.x + threadIdx.x;
    if (idx >= BATCH*NIN) return;
    int b = idx / NIN;
    int i = idx - b*NIN;
    float xv = x[idx];

    __half hh = __float2half_rn(xv);
    g_Axh[idx] = hh;
    g_Axl[idx] = __float2half_rn(xv - __half2float(hh));

    float tpos = (xv + 2.2f) * 2.5f;     // (xv - gridpt(0)) / 0.4
    float fj = floorf(tpos);
    int j = (int)fj;
    float u = tpos - fj;
    float w0 = 0.0f, w1 = 0.0f, w2 = 0.0f, w3 = 0.0f;
    if (j >= 0 && j <= 10){
        float u2 = u*u, u3 = u2*u;
        float om = 1.0f - u;
        w0 = om*om*om * (1.0f/6.0f);
        w1 = (3.0f*u3 - 6.0f*u2 + 4.0f) * (1.0f/6.0f);
        w2 = (-3.0f*u3 + 3.0f*u2 + 3.0f*u + 1.0f) * (1.0f/6.0f);
        w3 = u3 * (1.0f/6.0f);
    }
    float bas[8];
    #pragma unroll
    for (int c = 0; c < 8; c++){
        float val = 0.0f;
        val = (c == j-3) ? w0 : val;
        val = (c == j-2) ? w1 : val;
        val = (c == j-1) ? w2 : val;
        val = (c == j  ) ? w3 : val;
        bas[c] = val;
    }

    float v[8] = { bas[0], bas[2], bas[4], bas[6], bas[1], bas[3], bas[5], bas[7] };

    __half hi4[4], lo4[4];
    uint32_t metab = 0;
    #pragma unroll
    for (int g = 0; g < 2; g++){
        int i0 = -1, i1 = -1;
        float v0 = 0.0f, v1 = 0.0f;
        #pragma unroll
        for (int jj = 0; jj < 4; jj++){
            float w = v[4*g + jj];
            if (w != 0.0f){
                if (i0 < 0){ i0 = jj; v0 = w; }
                else if (i1 < 0){ i1 = jj; v1 = w; }
            }
        }
        if (i0 < 0){ i0 = 0; i1 = 1; }
        else if (i1 < 0){
            if (i0 < 3){ i1 = i0 + 1; }
            else { v1 = v0; v0 = 0.0f; i0 = 2; i1 = 3; }
        }
        __half h0 = __float2half_rn(v0), h1 = __float2half_rn(v1);
        hi4[2*g+0] = h0; hi4[2*g+1] = h1;
        lo4[2*g+0] = __float2half_rn(v0 - __half2float(h0));
        lo4[2*g+1] = __float2half_rn(v1 - __half2float(h1));
        metab |= (uint32_t)((i1 << 2) | i0) << (4*g);
    }
    size_t off = (size_t)b*4*NIN + (size_t)i*4;
    *reinterpret_cast<uint64_t*>(&g_Bch[off]) = *reinterpret_cast<const uint64_t*>(hi4);
    *reinterpret_cast<uint64_t*>(&g_Bcl[off]) = *reinterpret_cast<const uint64_t*>(lo4);
    g_Mb[(size_t)b*NIN + i] = (uint8_t)metab;
}

// ---------------- expand W: base_w hi/lo + parity-permuted quantized spline w ----------------
__global__ void expandW_sp(const float* __restrict__ bw, const float* __restrict__ sw, int NIN){
    int idx = blockIdx.x*blockDim.x + threadIdx.x;
    if (idx >= WID*NIN) return;
    int o = idx / NIN;
    int i = idx - o*NIN;

    float w = bw[idx];
    __half wh = __float2half_rn(w);
    g_Wxh[idx] = wh;
    g_Wxl[idx] = __float2half_rn(w - __half2float(wh));

    const int perm[8] = {0,2,4,6,1,3,5,7};
    const float* sp = sw + (size_t)idx*8;
    __half q8[8];
    #pragma unroll
    for (int j=0;j<8;j++)
        q8[j] = __float2half_rn(rintf(sp[perm[j]] * 32.0f) * 0.03125f);   // exact fp16
    size_t off = (size_t)o*8*NIN + (size_t)i*8;
    *reinterpret_cast<uint4*>(&g_Ws[off]) = *reinterpret_cast<const uint4*>(q8);
}

// ---------------- huxley_rd + trig_unfolding (1 block per row) ----------------
#define FN 1024
#define HT 512

__global__ void __launch_bounds__(HT) huxley_kernel(
    const float* __restrict__ X,
    const float* __restrict__ sgate,
    const float* __restrict__ dk,
    const float* __restrict__ a_p,
    const float* __restrict__ gamma_p,
    const float* __restrict__ tau_p,
    const float* __restrict__ vel_p,
    const float* __restrict__ gcve,
    const float* __restrict__ chir,
    float* __restrict__ out)
{
    __shared__ float2 Z[FN];
    __shared__ float2 TW[FN/2];
    __shared__ float  mg[FN/2 + 1];
    __shared__ float  red[HT];

    const int row = blockIdx.x;
    const int t = threadIdx.x;
    const float PI = 3.14159265358979323846f;

    for (int i=t;i<FN/2;i+=HT){
        float s,c;
        sincosf(-2.0f*PI*(float)i/(float)FN, &s, &c);
        TW[i] = make_float2(c, s);
    }
    for (int i=t;i<FN;i+=HT){
        unsigned r = __brev((unsigned)i) >> 22;
        Z[r] = make_float2(X[(size_t)row*FN + i], 0.0f);
    }
    __syncthreads();

    for (int s=0;s<10;s++){
        int half = 1<<s;
        for (int j=t;j<FN/2;j+=HT){
            int pos = j & (half-1);
            int i0 = ((j >> s) << (s+1)) + pos;
            int i1 = i0 + half;
            float2 w = TW[pos << (9-s)];
            float2 a = Z[i0], b = Z[i1];
            float2 wb = make_float2(w.x*b.x - w.y*b.y, w.x*b.y + w.y*b.x);
            Z[i0] = make_float2(a.x+wb.x, a.y+wb.y);
            Z[i1] = make_float2(a.x-wb.x, a.y-wb.y);
        }
        __syncthreads();
    }

    float v = vel_p[0];
    for (int k=t;k<=FN/2;k+=HT){
        float2 F = Z[k];
        float g = 1.0f/(1.0f + expf(-sgate[k]));
        float og = 1.0f - g;
        float ps, pc;
        sincosf(-2.0f*PI*(float)k*v/(float)FN, &ps, &pc);
        float2 nef = make_float2(F.x*og, F.y*og);
        float2 S = make_float2(nef.x*pc - nef.y*ps, nef.x*ps + nef.y*pc);
        float2 E = make_float2(F.x*g, F.y*g);
        if (k==0 || k==FN/2){
            mg[k] = fabsf(S.x);
            Z[k] = make_float2(E.x, S.x);
        } else {
            mg[k] = sqrtf(nef.x*nef.x + nef.y*nef.y);
            Z[k]    = make_float2(E.x - S.y, E.y + S.x);
            Z[FN-k] = make_float2(E.x + S.y, S.x - E.y);
        }
    }
    __syncthreads();

    float ls=0.0f, lmin=3.4e38f;
    for (int k=t;k<=FN/2;k+=HT){ ls += mg[k]; lmin = fminf(lmin, mg[k]); }
    red[t]=ls; __syncthreads();
    for (int o=HT/2;o>0;o>>=1){ if(t<o) red[t]+=red[t+o]; __syncthreads(); }
    float mean = red[0] / 513.0f; __syncthreads();
    red[t]=lmin; __syncthreads();
    for (int o=HT/2;o>0;o>>=1){ if(t<o) red[t]=fminf(red[t],red[t+o]); __syncthreads(); }
    float lam_min = red[0]; __syncthreads();
    float lv=0.0f;
    for (int k=t;k<=FN/2;k+=HT){ float d = mg[k]-mean; lv += d*d; }
    red[t]=lv; __syncthreads();
    for (int o=HT/2;o>0;o>>=1){ if(t<o) red[t]+=red[t+o]; __syncthreads(); }
    float var = red[0] / 512.0f; __syncthreads();

    for (int i=t;i<FN;i+=HT){
        unsigned r = __brev((unsigned)i) >> 22;
        if (i < (int)r){ float2 tmp = Z[i]; Z[i]=Z[r]; Z[r]=tmp; }
    }
    __syncthreads();
    for (int s=0;s<10;s++){
        int half = 1<<s;
        for (int j=t;j<FN/2;j+=HT){
            int pos = j & (half-1);
            int i0 = ((j >> s) << (s+1)) + pos;
            int i1 = i0 + half;
            float2 w = TW[pos << (9-s)];
            w.y = -w.y;
            float2 a = Z[i0], b = Z[i1];
            float2 wb = make_float2(w.x*b.x - w.y*b.y, w.x*b.y + w.y*b.x);
            Z[i0] = make_float2(a.x+wb.x, a.y+wb.y);
            Z[i1] = make_float2(a.x-wb.x, a.y-wb.y);
        }
        __syncthreads();
    }

    const float scale = 1.0f/(float)FN;
    float lt = 0.0f;
    for (int n=t;n<FN;n+=HT){ float hh = Z[n].y*scale; lt += hh*hh; }
    red[t]=lt; __syncthreads();
    for (int o=HT/2;o>0;o>>=1){ if(t<o) red[t]+=red[t+o]; __syncthreads(); }
    float tr_c = red[0]; __syncthreads();

    float tau = tau_p[0], gam = gamma_p[0], a = a_p[0];
    float k0 = dk[0], k1 = dk[1], k2 = dk[2];
    float gp = gcve[row];
    float ach = fabsf(chir[row]);

    float det = var + 1e-6f;
    float sq = sqrtf(det);
    float denom = 2.0f*(sq*sq*sq) + 1e-8f;
    float cos3 = (3.0f*gp - tr_c/tau) / denom;
    cos3 = fminf(0.999f, fmaxf(-0.999f, cos3));
    float phi = acosf(cos3) / 3.0f;
    float amp = 2.0f*sqrtf(lam_min/3.0f + 1e-8f);
    float c0 = amp * cosf(phi);
    float c1 = amp * cosf(phi + 2.0f*PI/3.0f) * expf(-ach);
    float c2 = amp * cosf(phi + 4.0f*PI/3.0f) * expf(-2.0f*ach);
    float e0=fabsf(c0), e1=fabsf(c1), e2=fabsf(c2);
    float cb = c0; float eb = e0;
    if (e1 > eb){ cb=c1; eb=e1; }
    if (e2 > eb){ cb=c2; }

    for (int n=t;n<FN;n+=HT){
        float e  = Z[n].x*scale;
        float em = (n>0)      ? Z[n-1].x*scale : 0.0f;
        float ep = (n<FN-1)   ? Z[n+1].x*scale : 0.0f;
        float reac = e*(e-a)*(1.0f-e);
        float dif  = k0*em + k1*e + k2*ep;
        float enx  = e + 0.1f*(reac + gam*dif);
        float hh   = Z[n].y*scale;
        float s    = enx + cb*hh;
        float sg   = 1.0f/(1.0f+expf(-s));
        out[(size_t)row*FN + n] = sg*s;
    }
}

// ---------------- launcher ----------------
extern "C" void kernel_launch(void* const* d_in, const int* in_sizes, int n_in,
                              void* d_out, int out_size) {
    const float* c   = (const float*)d_in[0];
    const float* bw0 = (const float*)d_in[1];
    const float* sw0 = (const float*)d_in[2];
    const float* bw1 = (const float*)d_in[3];
    const float* sw1 = (const float*)d_in[4];
    const float* bw2 = (const float*)d_in[5];
    const float* sw2 = (const float*)d_in[6];
    const float* sg  = (const float*)d_in[7];
    const float* dk  = (const float*)d_in[8];
    const float* ap  = (const float*)d_in[9];
    const float* gm  = (const float*)d_in[10];
    const float* td  = (const float*)d_in[11];
    const float* sv  = (const float*)d_in[12];
    const float* gp  = (const float*)d_in[13];
    const float* ch  = (const float*)d_in[14];

    void *pAxh, *pAxl, *pBch, *pBcl, *pMb, *pWxh, *pWxl, *pWs;
    float *X0, *X1;
    cudaGetSymbolAddress(&pAxh, g_Axh);
    cudaGetSymbolAddress(&pAxl, g_Axl);
    cudaGetSymbolAddress(&pBch, g_Bch);
    cudaGetSymbolAddress(&pBcl, g_Bcl);
    cudaGetSymbolAddress(&pMb,  g_Mb);
    cudaGetSymbolAddress(&pWxh, g_Wxh);
    cudaGetSymbolAddress(&pWxl, g_Wxl);
    cudaGetSymbolAddress(&pWs,  g_Ws);
    cudaGetSymbolAddress((void**)&X0, g_X0);
    cudaGetSymbolAddress((void**)&X1, g_X1);

    cudaFuncSetAttribute(gemm_sp,      cudaFuncAttributeMaxDynamicSharedMemorySize, SP_SMEM);
    cudaFuncSetAttribute(gemm_f16base, cudaFuncAttributeMaxDynamicSharedMemorySize, FB_SMEM);

    dim3 gblk(WID/128, BATCH/256);   // (8, 16) = 128 CTAs, single wave

    struct LayerCfg { const float* bw; const float* sw; const float* in; float* out; int nin; };
    LayerCfg L[3] = {
        { bw0, sw0, c,  X0, 512  },
        { bw1, sw1, X0, X1, 1024 },
        { bw2, sw2, X1, X0, 1024 },
    };

    for (int l = 0; l < 3; l++) {
        int NIN = L[l].nin;

        expandW_sp<<<(WID*NIN + 255)/256, 256>>>(L[l].bw, L[l].sw, NIN);
        expandA_sp<<<(BATCH*NIN + 255)/256, 256>>>(L[l].in, NIN);

        gemm_sp<<<gblk, 256, SP_SMEM>>>(
            (const __half*)pBch, (const __half*)pBcl, (const uint8_t*)pMb,
            (const __half*)pWs, L[l].out, NIN);

        gemm_f16base<<<gblk, 256, FB_SMEM>>>(
            (const __half*)pAxh, (const __half*)pAxl,
            (const __half*)pWxh, (const __half*)pWxl,
            L[l].out, NIN);
    }

    huxley_kernel<<<BATCH, HT>>>(X0, sg, dk, ap, gm, td, sv, gp, ch, (float*)d_out);
}

// round 17
// speedup vs baseline: 1.0240x; 1.0240x over previous
#include <cuda_runtime.h>
#include <cuda_fp16.h>
#include <cstdint>

#define BATCH 4096
#define WID   1024
#define NMAX  1024

// ---------------- scratch (device globals: allowed) ----------------
__device__ __half  g_Axh[(size_t)BATCH*NMAX];       // x hi (fp16)
__device__ __half  g_Axl[(size_t)BATCH*NMAX];       // x lo (fp16)
__device__ __half  g_Bch[(size_t)BATCH*4*NMAX];     // compressed basis hi (2:4)
__device__ __half  g_Bcl[(size_t)BATCH*4*NMAX];     // compressed basis lo
__device__ uint8_t g_Mb [(size_t)BATCH*NMAX];       // metadata: 1 byte / input
__device__ __half  g_Wxh[(size_t)WID*NMAX];         // base_w hi
__device__ __half  g_Wxl[(size_t)WID*NMAX];         // base_w lo
__device__ __half  g_Ws [(size_t)WID*8*NMAX];       // parity-permuted quantized spline w (exact fp16)
__device__ float   g_X0[(size_t)BATCH*WID];
__device__ float   g_X1[(size_t)BATCH*WID];

// ---------------- helpers ----------------
__device__ __forceinline__ uint32_t smem_u32(const void* p){
    return (uint32_t)__cvta_generic_to_shared(p);
}
__device__ __forceinline__ void cpa16(uint32_t dst, const void* src){
    asm volatile("cp.async.ca.shared.global [%0], [%1], 16;\n" :: "r"(dst), "l"(src));
}
__device__ __forceinline__ void ldsm4(uint32_t* r, uint32_t addr){
    asm volatile("ldmatrix.sync.aligned.m8n8.x4.shared.b16 {%0,%1,%2,%3}, [%4];\n"
        : "=r"(r[0]), "=r"(r[1]), "=r"(r[2]), "=r"(r[3]) : "r"(addr));
}
#define MMA16816(d, a, b0, b1)                                                        \
    asm volatile("mma.sync.aligned.m16n8k16.row.col.f32.f16.f16.f32 "                 \
        "{%0,%1,%2,%3},{%4,%5,%6,%7},{%8,%9},{%0,%1,%2,%3};\n"                        \
        : "+f"((d)[0]), "+f"((d)[1]), "+f"((d)[2]), "+f"((d)[3])                      \
        : "r"((a)[0]), "r"((a)[1]), "r"((a)[2]), "r"((a)[3]), "r"(b0), "r"(b1))
// sparse 2:4 fp16 mma, k32, ordered metadata, selector 0
#define MMASP(d, a, b0, b1, b2, b3, e)                                                \
    asm volatile("mma.sp::ordered_metadata.sync.aligned.m16n8k32.row.col.f32.f16.f16.f32 " \
        "{%0,%1,%2,%3},{%4,%5,%6,%7},{%8,%9,%10,%11},{%0,%1,%2,%3},%12,0x0;\n"        \
        : "+f"((d)[0]), "+f"((d)[1]), "+f"((d)[2]), "+f"((d)[3])                      \
        : "r"((a)[0]), "r"((a)[1]), "r"((a)[2]), "r"((a)[3]),                         \
          "r"(b0), "r"(b1), "r"(b2), "r"(b3), "r"(e))

// swizzled smem address: 128B rows, 16B chunk index XOR (row % 8); k in halves
__device__ __forceinline__ uint32_t swaddr(uint32_t base, int r, int k){
    return base + (r << 7) + ((((k >> 3) ^ r) & 7) << 4) + ((k & 7) << 1);
}

// 256-thread tile loaders
__device__ __forceinline__ void ld256_t256(uint32_t dstBase, const int8_t* g, int strideBytes){
    int t = threadIdx.x;
    #pragma unroll
    for (int i = 0; i < 8; i++){
        int q = t + i*256;
        int r = q >> 3, c = q & 7;
        uint32_t d = dstBase + (r << 7) + (((c ^ r) & 7) << 4);
        cpa16(d, g + (size_t)r * strideBytes + (c << 4));
    }
}
__device__ __forceinline__ void ld128_t256(uint32_t dstBase, const int8_t* g, int strideBytes){
    int t = threadIdx.x;
    #pragma unroll
    for (int i = 0; i < 4; i++){
        int q = t + i*256;
        int r = q >> 3, c = q & 7;
        uint32_t d = dstBase + (r << 7) + (((c ^ r) & 7) << 4);
        cpa16(d, g + (size_t)r * strideBytes + (c << 4));
    }
}

// ============================================================
// sparse spline GEMM (R15 proven-best): C = Bhi@Ws + Blo@Ws
// CTA tile M=256 x N=128, 256 threads (8 warps), warp tile 64x64
// chunk = 16 inputs (true k=128, compressed k=64); 2 stages
// metadata semantics: H4 (diag-verified)
// ============================================================
#define SP_STAGE 102400
#define SP_SMEM  (2*SP_STAGE)

__global__ void __launch_bounds__(256, 1) gemm_sp(
    const __half* __restrict__ Bch, const __half* __restrict__ Bcl,
    const uint8_t* __restrict__ Mb, const __half* __restrict__ Ws,
    float* __restrict__ C, int NIN)
{
    extern __shared__ __align__(128) char smem[];
    uint32_t sb = smem_u32(smem);
    const int tid = threadIdx.x, wid = tid >> 5, lane = tid & 31;
    const int wm = wid & 3, wn = wid >> 2;      // 4x2 warp grid, warp tile 64x64
    const int bm = blockIdx.y * 256, bn = blockIdx.x * 128;
    const int NC = NIN / 16;
    const int msh = (lane & 1) << 4;

    const int8_t*  gH = (const int8_t*)(Bch + (size_t)bm * 4 * NIN);
    const int8_t*  gL = (const int8_t*)(Bcl + (size_t)bm * 4 * NIN);
    const uint8_t* gM = Mb + (size_t)bm * NIN;
    const int8_t*  gW = (const int8_t*)(Ws + (size_t)bn * 8 * NIN);

    auto load_chunk = [&](int c){
        uint32_t base = sb + (c & 1) * SP_STAGE;
        ld256_t256(base,          gH + (size_t)c*128, 8*NIN);
        ld256_t256(base + 32768,  gL + (size_t)c*128, 8*NIN);
        cpa16(base + 65536 + tid*16, gM + (size_t)tid*NIN + c*16);
        ld128_t256(base + 69632,  gW + (size_t)c*256,       16*NIN);
        ld128_t256(base + 86016,  gW + (size_t)c*256 + 128, 16*NIN);
    };

    float acc[4][8][4];
    #pragma unroll
    for (int i=0;i<4;i++)
        #pragma unroll
        for (int j=0;j<8;j++)
            #pragma unroll
            for (int q=0;q<4;q++) acc[i][j][q]=0.0f;

    load_chunk(0); asm volatile("cp.async.commit_group;\n" ::: "memory");
    load_chunk(1); asm volatile("cp.async.commit_group;\n" ::: "memory");

    const int nbase = wn*64 + ((lane >> 4) << 3) + (lane & 7);

    for (int c = 0; c < NC; c++){
        asm volatile("cp.async.wait_group 1;\n" ::: "memory");
        __syncthreads();
        uint32_t base = sb + (c & 1) * SP_STAGE;
        uint32_t sH = base, sL = base + 32768, sM = base + 65536, sW = base + 69632;

        // hoisted metadata: 2x LDS.128 per (i), register extraction, branch-free
        uint32_t meta[4][4];
        #pragma unroll
        for (int i = 0; i < 4; i++){
            int mr = wm*64 + i*16 + (lane >> 2);
            uint32_t a0,a1,a2,a3, c0,c1,c2,c3;
            asm volatile("ld.shared.v4.u32 {%0,%1,%2,%3}, [%4];"
                : "=r"(a0),"=r"(a1),"=r"(a2),"=r"(a3) : "r"(sM + mr*16));
            asm volatile("ld.shared.v4.u32 {%0,%1,%2,%3}, [%4];"
                : "=r"(c0),"=r"(c1),"=r"(c2),"=r"(c3) : "r"(sM + (mr+8)*16));
            meta[i][0] = ((a0>>msh)&0xFFFFu) | (((c0>>msh)&0xFFFFu)<<16);
            meta[i][1] = ((a1>>msh)&0xFFFFu) | (((c1>>msh)&0xFFFFu)<<16);
            meta[i][2] = ((a2>>msh)&0xFFFFu) | (((c2>>msh)&0xFFFFu)<<16);
            meta[i][3] = ((a3>>msh)&0xFFFFu) | (((c3>>msh)&0xFFFFu)<<16);
        }

        #pragma unroll
        for (int s = 0; s < 4; s++){
            int ka = s*16 + ((lane >> 4) << 3);              // compressed col offset
            uint32_t ah[4][4], al[4][4];
            #pragma unroll
            for (int i = 0; i < 4; i++){
                int r = wm*64 + i*16 + (lane & 15);
                ldsm4(ah[i], swaddr(sH, r, ka));
                ldsm4(al[i], swaddr(sL, r, ka));
            }
            int kb = ((s & 1) << 5) + (((lane >> 3) & 1) << 3);
            uint32_t wtb = sW + ((s >> 1) << 14);
            #pragma unroll
            for (int p = 0; p < 4; p++){
                int n = nbase + p*16;
                uint32_t b0[4], b1[4];
                ldsm4(b0, swaddr(wtb, n, kb));
                ldsm4(b1, swaddr(wtb, n, kb + 16));
                // hi pass
                #pragma unroll
                for (int i = 0; i < 4; i++){
                    MMASP(acc[i][2*p+0], ah[i], b0[0], b0[1], b1[0], b1[1], meta[i][s]);
                    MMASP(acc[i][2*p+1], ah[i], b0[2], b0[3], b1[2], b1[3], meta[i][s]);
                }
                // lo pass (same B frags + metadata)
                #pragma unroll
                for (int i = 0; i < 4; i++){
                    MMASP(acc[i][2*p+0], al[i], b0[0], b0[1], b1[0], b1[1], meta[i][s]);
                    MMASP(acc[i][2*p+1], al[i], b0[2], b0[3], b1[2], b1[3], meta[i][s]);
                }
            }
        }
        __syncthreads();
        if (c + 2 < NC) load_chunk(c + 2);
        asm volatile("cp.async.commit_group;\n" ::: "memory");
    }

    // epilogue: write C
    #pragma unroll
    for (int i = 0; i < 4; i++){
        int row = bm + wm*64 + i*16 + (lane >> 2);
        #pragma unroll
        for (int j = 0; j < 8; j++){
            int col = bn + wn*64 + j*8 + ((lane & 3) << 1);
            float* p = C + (size_t)row * WID + col;
            *reinterpret_cast<float2*>(p)         = make_float2(acc[i][j][0], acc[i][j][1]);
            *reinterpret_cast<float2*>(p + 8*WID) = make_float2(acc[i][j][2], acc[i][j][3]);
        }
    }
}

// ============================================================
// fp16 base GEMM (R16 measured-best): split 3-pass, K = NIN, C +=
// CTA tile M=256 x N=128, 256 threads (8 warps), warp tile 64x64
// ============================================================
#define FB_STAGE 98304
#define FB_SMEM  (2*FB_STAGE)

__global__ void __launch_bounds__(256, 1) gemm_f16base(
    const __half* __restrict__ Axh, const __half* __restrict__ Axl,
    const __half* __restrict__ Wxh, const __half* __restrict__ Wxl,
    float* __restrict__ C, int K)
{
    extern __shared__ __align__(128) char smem[];
    uint32_t sb = smem_u32(smem);
    const int tid = threadIdx.x, wid = tid >> 5, lane = tid & 31;
    const int wm = wid & 3, wn = wid >> 2;      // 4x2 warp grid, warp tile 64x64
    const int bm = blockIdx.y * 256, bn = blockIdx.x * 128;
    const int NC = K / 64;

    const int8_t* gAh = (const int8_t*)(Axh + (size_t)bm * K);
    const int8_t* gAl = (const int8_t*)(Axl + (size_t)bm * K);
    const int8_t* gWh = (const int8_t*)(Wxh + (size_t)bn * K);
    const int8_t* gWl = (const int8_t*)(Wxl + (size_t)bn * K);

    auto load_chunk = [&](int c){
        uint32_t base = sb + (c & 1) * FB_STAGE;
        int kb = c * 128;                      // 64 halves = 128 bytes
        ld256_t256(base,         gAh + kb, 2*K);
        ld256_t256(base + 32768, gAl + kb, 2*K);
        ld128_t256(base + 65536, gWh + kb, 2*K);
        ld128_t256(base + 81920, gWl + kb, 2*K);
    };

    float acc[4][8][4];
    #pragma unroll
    for (int i=0;i<4;i++)
        #pragma unroll
        for (int j=0;j<8;j++)
            #pragma unroll
            for (int q=0;q<4;q++) acc[i][j][q]=0.0f;

    load_chunk(0); asm volatile("cp.async.commit_group;\n" ::: "memory");
    load_chunk(1); asm volatile("cp.async.commit_group;\n" ::: "memory");

    const int nbase = wn*64 + ((lane >> 4) << 3) + (lane & 7);

    for (int c = 0; c < NC; c++){
        asm volatile("cp.async.wait_group 1;\n" ::: "memory");
        __syncthreads();
        uint32_t base = sb + (c & 1) * FB_STAGE;
        uint32_t sAh = base, sAl = base + 32768, sWh = base + 65536, sWl = base + 81920;

        #pragma unroll
        for (int ks = 0; ks < 4; ks++){
            int k0 = ks * 16;
            int ka = k0 + ((lane >> 4) << 3);
            int kb = k0 + (((lane >> 3) & 1) << 3);
            uint32_t ah[4][4], al[4][4];
            #pragma unroll
            for (int i = 0; i < 4; i++){
                int r = wm*64 + i*16 + (lane & 15);
                ldsm4(ah[i], swaddr(sAh, r, ka));
                ldsm4(al[i], swaddr(sAl, r, ka));
            }
            #pragma unroll
            for (int p = 0; p < 4; p++){
                int n = nbase + p*16;
                uint32_t bh[4], bl[4];
                ldsm4(bh, swaddr(sWh, n, kb));
                ldsm4(bl, swaddr(sWl, n, kb));
                // pass 1: Ahi * Whi
                #pragma unroll
                for (int i = 0; i < 4; i++){
                    MMA16816(acc[i][2*p+0], ah[i], bh[0], bh[1]);
                    MMA16816(acc[i][2*p+1], ah[i], bh[2], bh[3]);
                }
                // pass 2: Alo * Whi
                #pragma unroll
                for (int i = 0; i < 4; i++){
                    MMA16816(acc[i][2*p+0], al[i], bh[0], bh[1]);
                    MMA16816(acc[i][2*p+1], al[i], bh[2], bh[3]);
                }
                // pass 3: Ahi * Wlo
                #pragma unroll
                for (int i = 0; i < 4; i++){
                    MMA16816(acc[i][2*p+0], ah[i], bl[0], bl[1]);
                    MMA16816(acc[i][2*p+1], ah[i], bl[2], bl[3]);
                }
            }
        }
        __syncthreads();
        if (c + 2 < NC) load_chunk(c + 2);
        asm volatile("cp.async.commit_group;\n" ::: "memory");
    }

    // epilogue: C +=
    #pragma unroll
    for (int i = 0; i < 4; i++){
        int row = bm + wm*64 + i*16 + (lane >> 2);
        #pragma unroll
        for (int j = 0; j < 8; j++){
            int col = bn + wn*64 + j*8 + ((lane & 3) << 1);
            float* p = C + (size_t)row * WID + col;
            float2 o0 = *reinterpret_cast<float2*>(p);
            float2 o1 = *reinterpret_cast<float2*>(p + 8*WID);
            *reinterpret_cast<float2*>(p)         = make_float2(o0.x + acc[i][j][0], o0.y + acc[i][j][1]);
            *reinterpret_cast<float2*>(p + 8*WID) = make_float2(o1.x + acc[i][j][2], o1.y + acc[i][j][3]);
        }
    }
}

// ---------------- expand A: closed-form cubic B-spline (uniform grid) ----------------
__global__ void expandA_sp(const float* __restrict__ x, int NIN){
    int idx = blockIdx.x*blockDim.x + threadIdx.x;
    if (idx >= BATCH*NIN) return;
    int b = idx / NIN;
    int i = idx - b*NIN;
    float xv = x[idx];

    __half hh = __float2half_rn(xv);
    g_Axh[idx] = hh;
    g_Axl[idx] = __float2half_rn(xv - __half2float(hh));

    float tpos = (xv + 2.2f) * 2.5f;     // (xv - gridpt(0)) / 0.4
    float fj = floorf(tpos);
    int j = (int)fj;
    float u = tpos - fj;
    float w0 = 0.0f, w1 = 0.0f, w2 = 0.0f, w3 = 0.0f;
    if (j >= 0 && j <= 10){
        float u2 = u*u, u3 = u2*u;
        float om = 1.0f - u;
        w0 = om*om*om * (1.0f/6.0f);
        w1 = (3.0f*u3 - 6.0f*u2 + 4.0f) * (1.0f/6.0f);
        w2 = (-3.0f*u3 + 3.0f*u2 + 3.0f*u + 1.0f) * (1.0f/6.0f);
        w3 = u3 * (1.0f/6.0f);
    }
    float bas[8];
    #pragma unroll
    for (int c = 0; c < 8; c++){
        float val = 0.0f;
        val = (c == j-3) ? w0 : val;
        val = (c == j-2) ? w1 : val;
        val = (c == j-1) ? w2 : val;
        val = (c == j  ) ? w3 : val;
        bas[c] = val;
    }

    float v[8] = { bas[0], bas[2], bas[4], bas[6], bas[1], bas[3], bas[5], bas[7] };

    __half hi4[4], lo4[4];
    uint32_t metab = 0;
    #pragma unroll
    for (int g = 0; g < 2; g++){
        int i0 = -1, i1 = -1;
        float v0 = 0.0f, v1 = 0.0f;
        #pragma unroll
        for (int jj = 0; jj < 4; jj++){
            float w = v[4*g + jj];
            if (w != 0.0f){
                if (i0 < 0){ i0 = jj; v0 = w; }
                else if (i1 < 0){ i1 = jj; v1 = w; }
            }
        }
        if (i0 < 0){ i0 = 0; i1 = 1; }
        else if (i1 < 0){
            if (i0 < 3){ i1 = i0 + 1; }
            else { v1 = v0; v0 = 0.0f; i0 = 2; i1 = 3; }
        }
        __half h0 = __float2half_rn(v0), h1 = __float2half_rn(v1);
        hi4[2*g+0] = h0; hi4[2*g+1] = h1;
        lo4[2*g+0] = __float2half_rn(v0 - __half2float(h0));
        lo4[2*g+1] = __float2half_rn(v1 - __half2float(h1));
        metab |= (uint32_t)((i1 << 2) | i0) << (4*g);
    }
    size_t off = (size_t)b*4*NIN + (size_t)i*4;
    *reinterpret_cast<uint64_t*>(&g_Bch[off]) = *reinterpret_cast<const uint64_t*>(hi4);
    *reinterpret_cast<uint64_t*>(&g_Bcl[off]) = *reinterpret_cast<const uint64_t*>(lo4);
    g_Mb[(size_t)b*NIN + i] = (uint8_t)metab;
}

// ---------------- expand W: base_w hi/lo + parity-permuted quantized spline w ----------------
__global__ void expandW_sp(const float* __restrict__ bw, const float* __restrict__ sw, int NIN){
    int idx = blockIdx.x*blockDim.x + threadIdx.x;
    if (idx >= WID*NIN) return;
    int o = idx / NIN;
    int i = idx - o*NIN;

    float w = bw[idx];
    __half wh = __float2half_rn(w);
    g_Wxh[idx] = wh;
    g_Wxl[idx] = __float2half_rn(w - __half2float(wh));

    const int perm[8] = {0,2,4,6,1,3,5,7};
    const float* sp = sw + (size_t)idx*8;
    __half q8[8];
    #pragma unroll
    for (int j=0;j<8;j++)
        q8[j] = __float2half_rn(rintf(sp[perm[j]] * 32.0f) * 0.03125f);   // exact fp16
    size_t off = (size_t)o*8*NIN + (size_t)i*8;
    *reinterpret_cast<uint4*>(&g_Ws[off]) = *reinterpret_cast<const uint4*>(q8);
}

// ---------------- huxley_rd + trig_unfolding (1 block per row, HT=256 proven-best) ----------------
#define FN 1024
#define HT 256

__global__ void __launch_bounds__(HT) huxley_kernel(
    const float* __restrict__ X,
    const float* __restrict__ sgate,
    const float* __restrict__ dk,
    const float* __restrict__ a_p,
    const float* __restrict__ gamma_p,
    const float* __restrict__ tau_p,
    const float* __restrict__ vel_p,
    const float* __restrict__ gcve,
    const float* __restrict__ chir,
    float* __restrict__ out)
{
    __shared__ float2 Z[FN];
    __shared__ float2 TW[FN/2];
    __shared__ float  mg[FN/2 + 1];
    __shared__ float  red[HT];

    const int row = blockIdx.x;
    const int t = threadIdx.x;
    const float PI = 3.14159265358979323846f;

    for (int i=t;i<FN/2;i+=HT){
        float s,c;
        sincosf(-2.0f*PI*(float)i/(float)FN, &s, &c);
        TW[i] = make_float2(c, s);
    }
    for (int i=t;i<FN;i+=HT){
        unsigned r = __brev((unsigned)i) >> 22;
        Z[r] = make_float2(X[(size_t)row*FN + i], 0.0f);
    }
    __syncthreads();

    for (int s=0;s<10;s++){
        int half = 1<<s;
        for (int j=t;j<FN/2;j+=HT){
            int pos = j & (half-1);
            int i0 = ((j >> s) << (s+1)) + pos;
            int i1 = i0 + half;
            float2 w = TW[pos << (9-s)];
            float2 a = Z[i0], b = Z[i1];
            float2 wb = make_float2(w.x*b.x - w.y*b.y, w.x*b.y + w.y*b.x);
            Z[i0] = make_float2(a.x+wb.x, a.y+wb.y);
            Z[i1] = make_float2(a.x-wb.x, a.y-wb.y);
        }
        __syncthreads();
    }

    float v = vel_p[0];
    for (int k=t;k<=FN/2;k+=HT){
        float2 F = Z[k];
        float g = 1.0f/(1.0f + expf(-sgate[k]));
        float og = 1.0f - g;
        float ps, pc;
        sincosf(-2.0f*PI*(float)k*v/(float)FN, &ps, &pc);
        float2 nef = make_float2(F.x*og, F.y*og);
        float2 S = make_float2(nef.x*pc - nef.y*ps, nef.x*ps + nef.y*pc);
        float2 E = make_float2(F.x*g, F.y*g);
        if (k==0 || k==FN/2){
            mg[k] = fabsf(S.x);
            Z[k] = make_float2(E.x, S.x);
        } else {
            mg[k] = sqrtf(nef.x*nef.x + nef.y*nef.y);
            Z[k]    = make_float2(E.x - S.y, E.y + S.x);
            Z[FN-k] = make_float2(E.x + S.y, S.x - E.y);
        }
    }
    __syncthreads();

    float ls=0.0f, lmin=3.4e38f;
    for (int k=t;k<=FN/2;k+=HT){ ls += mg[k]; lmin = fminf(lmin, mg[k]); }
    red[t]=ls; __syncthreads();
    for (int o=HT/2;o>0;o>>=1){ if(t<o) red[t]+=red[t+o]; __syncthreads(); }
    float mean = red[0] / 513.0f; __syncthreads();
    red[t]=lmin; __syncthreads();
    for (int o=HT/2;o>0;o>>=1){ if(t<o) red[t]=fminf(red[t],red[t+o]); __syncthreads(); }
    float lam_min = red[0]; __syncthreads();
    float lv=0.0f;
    for (int k=t;k<=FN/2;k+=HT){ float d = mg[k]-mean; lv += d*d; }
    red[t]=lv; __syncthreads();
    for (int o=HT/2;o>0;o>>=1){ if(t<o) red[t]+=red[t+o]; __syncthreads(); }
    float var = red[0] / 512.0f; __syncthreads();

    for (int i=t;i<FN;i+=HT){
        unsigned r = __brev((unsigned)i) >> 22;
        if (i < (int)r){ float2 tmp = Z[i]; Z[i]=Z[r]; Z[r]=tmp; }
    }
    __syncthreads();
    for (int s=0;s<10;s++){
        int half = 1<<s;
        for (int j=t;j<FN/2;j+=HT){
            int pos = j & (half-1);
            int i0 = ((j >> s) << (s+1)) + pos;
            int i1 = i0 + half;
            float2 w = TW[pos << (9-s)];
            w.y = -w.y;
            float2 a = Z[i0], b = Z[i1];
            float2 wb = make_float2(w.x*b.x - w.y*b.y, w.x*b.y + w.y*b.x);
            Z[i0] = make_float2(a.x+wb.x, a.y+wb.y);
            Z[i1] = make_float2(a.x-wb.x, a.y-wb.y);
        }
        __syncthreads();
    }

    const float scale = 1.0f/(float)FN;
    float lt = 0.0f;
    for (int n=t;n<FN;n+=HT){ float hh = Z[n].y*scale; lt += hh*hh; }
    red[t]=lt; __syncthreads();
    for (int o=HT/2;o>0;o>>=1){ if(t<o) red[t]+=red[t+o]; __syncthreads(); }
    float tr_c = red[0]; __syncthreads();

    float tau = tau_p[0], gam = gamma_p[0], a = a_p[0];
    float k0 = dk[0], k1 = dk[1], k2 = dk[2];
    float gp = gcve[row];
    float ach = fabsf(chir[row]);

    float det = var + 1e-6f;
    float sq = sqrtf(det);
    float denom = 2.0f*(sq*sq*sq) + 1e-8f;
    float cos3 = (3.0f*gp - tr_c/tau) / denom;
    cos3 = fminf(0.999f, fmaxf(-0.999f, cos3));
    float phi = acosf(cos3) / 3.0f;
    float amp = 2.0f*sqrtf(lam_min/3.0f + 1e-8f);
    float c0 = amp * cosf(phi);
    float c1 = amp * cosf(phi + 2.0f*PI/3.0f) * expf(-ach);
    float c2 = amp * cosf(phi + 4.0f*PI/3.0f) * expf(-2.0f*ach);
    float e0=fabsf(c0), e1=fabsf(c1), e2=fabsf(c2);
    float cb = c0; float eb = e0;
    if (e1 > eb){ cb=c1; eb=e1; }
    if (e2 > eb){ cb=c2; }

    for (int n=t;n<FN;n+=HT){
        float e  = Z[n].x*scale;
        float em = (n>0)      ? Z[n-1].x*scale : 0.0f;
        float ep = (n<FN-1)   ? Z[n+1].x*scale : 0.0f;
        float reac = e*(e-a)*(1.0f-e);
        float dif  = k0*em + k1*e + k2*ep;
        float enx  = e + 0.1f*(reac + gam*dif);
        float hh   = Z[n].y*scale;
        float s    = enx + cb*hh;
        float sg   = 1.0f/(1.0f+expf(-s));
        out[(size_t)row*FN + n] = sg*s;
    }
}

// ---------------- launcher ----------------
extern "C" void kernel_launch(void* const* d_in, const int* in_sizes, int n_in,
                              void* d_out, int out_size) {
    const float* c   = (const float*)d_in[0];
    const float* bw0 = (const float*)d_in[1];
    const float* sw0 = (const float*)d_in[2];
    const float* bw1 = (const float*)d_in[3];
    const float* sw1 = (const float*)d_in[4];
    const float* bw2 = (const float*)d_in[5];
    const float* sw2 = (const float*)d_in[6];
    const float* sg  = (const float*)d_in[7];
    const float* dk  = (const float*)d_in[8];
    const float* ap  = (const float*)d_in[9];
    const float* gm  = (const float*)d_in[10];
    const float* td  = (const float*)d_in[11];
    const float* sv  = (const float*)d_in[12];
    const float* gp  = (const float*)d_in[13];
    const float* ch  = (const float*)d_in[14];

    void *pAxh, *pAxl, *pBch, *pBcl, *pMb, *pWxh, *pWxl, *pWs;
    float *X0, *X1;
    cudaGetSymbolAddress(&pAxh, g_Axh);
    cudaGetSymbolAddress(&pAxl, g_Axl);
    cudaGetSymbolAddress(&pBch, g_Bch);
    cudaGetSymbolAddress(&pBcl, g_Bcl);
    cudaGetSymbolAddress(&pMb,  g_Mb);
    cudaGetSymbolAddress(&pWxh, g_Wxh);
    cudaGetSymbolAddress(&pWxl, g_Wxl);
    cudaGetSymbolAddress(&pWs,  g_Ws);
    cudaGetSymbolAddress((void**)&X0, g_X0);
    cudaGetSymbolAddress((void**)&X1, g_X1);

    cudaFuncSetAttribute(gemm_sp,      cudaFuncAttributeMaxDynamicSharedMemorySize, SP_SMEM);
    cudaFuncSetAttribute(gemm_f16base, cudaFuncAttributeMaxDynamicSharedMemorySize, FB_SMEM);

    dim3 gblk(WID/128, BATCH/256);   // (8, 16) = 128 CTAs, single wave

    struct LayerCfg { const float* bw; const float* sw; const float* in; float* out; int nin; };
    LayerCfg L[3] = {
        { bw0, sw0, c,  X0, 512  },
        { bw1, sw1, X0, X1, 1024 },
        { bw2, sw2, X1, X0, 1024 },
    };

    for (int l = 0; l < 3; l++) {
        int NIN = L[l].nin;

        expandW_sp<<<(WID*NIN + 255)/256, 256>>>(L[l].bw, L[l].sw, NIN);
        expandA_sp<<<(BATCH*NIN + 255)/256, 256>>>(L[l].in, NIN);

        gemm_sp<<<gblk, 256, SP_SMEM>>>(
            (const __half*)pBch, (const __half*)pBcl, (const uint8_t*)pMb,
            (const __half*)pWs, L[l].out, NIN);

        gemm_f16base<<<gblk, 256, FB_SMEM>>>(
            (const __half*)pAxh, (const __half*)pAxl,
            (const __half*)pWxh, (const __half*)pWxl,
            L[l].out, NIN);
    }

    huxley_kernel<<<BATCH, HT>>>(X0, sg, dk, ap, gm, td, sv, gp, ch, (float*)d_out);
}